// round 5
// baseline (speedup 1.0000x reference)
#include <cuda_runtime.h>
#include <cuda_fp16.h>
#include <cstdint>

#define NN 100000
#define EE 1600000
#define HD 128
#define FIN 64
#define NLAYER 3
#define SCAN_BLK 1024
#define NSCAN ((NN + SCAN_BLK - 1) / SCAN_BLK)   // 98
#define NWELEM (FIN * HD + NLAYER * HD * HD)     // 57344
#define BST 40   // B smem stride (halves)

// ---------------- device scratch ----------------
__device__ float  g_dinv[NN];
__device__ int    g_cnt[NN];
__device__ int    g_rowptr[NN + 1];
__device__ int    g_cursor[NN];
__device__ int    g_blocksum[NSCAN + 1];
__device__ int2   g_csr[EE];               // {src, weight-as-int}
__device__ float  g_t[NN];
__device__ __half g_h16[(size_t)NN * HD];
__device__ __half g_h16b[(size_t)NN * HD];
__device__ __half g_WhiT[NWELEM];          // [n][k] fp16 hi
__device__ __half g_WloT[NWELEM];          // [n][k] fp16 lo

// ---------------- degree / norm / CSR build ----------------
__global__ void k_zero_cnt() {
    int i = blockIdx.x * blockDim.x + threadIdx.x;
    if (i < NN) g_cnt[i] = 0;
}
__global__ void k_hist(const int* __restrict__ dst) {
    int e = blockIdx.x * blockDim.x + threadIdx.x;
    if (e < EE) atomicAdd(&g_cnt[dst[e]], 1);
}
__global__ void k_dinv() {
    int i = blockIdx.x * blockDim.x + threadIdx.x;
    if (i < NN) g_dinv[i] = rsqrtf((float)(g_cnt[i] + 1));
}
__global__ void k_scan1() {
    __shared__ int sh[SCAN_BLK];
    int i = blockIdx.x * SCAN_BLK + threadIdx.x;
    int v = (i < NN) ? g_cnt[i] : 0;
    sh[threadIdx.x] = v;
    __syncthreads();
    int acc = v;
#pragma unroll
    for (int off = 1; off < SCAN_BLK; off <<= 1) {
        int t = (threadIdx.x >= off) ? sh[threadIdx.x - off] : 0;
        __syncthreads();
        acc += t;
        sh[threadIdx.x] = acc;
        __syncthreads();
    }
    if (i < NN) g_rowptr[i] = acc - v;
    if (threadIdx.x == SCAN_BLK - 1) g_blocksum[blockIdx.x] = acc;
}
__global__ void k_scan2() {
    __shared__ int sh[128];
    int i = threadIdx.x;
    int v = (i < NSCAN) ? g_blocksum[i] : 0;
    sh[i] = v;
    __syncthreads();
    int acc = v;
#pragma unroll
    for (int off = 1; off < 128; off <<= 1) {
        int t = (i >= off) ? sh[i - off] : 0;
        __syncthreads();
        acc += t;
        sh[i] = acc;
        __syncthreads();
    }
    if (i < NSCAN) g_blocksum[i] = acc - v;
}
__global__ void k_scan3() {
    int i = blockIdx.x * blockDim.x + threadIdx.x;
    if (i < NN) {
        int rp = g_rowptr[i] + g_blocksum[i / SCAN_BLK];
        g_rowptr[i] = rp;
        g_cursor[i] = rp;                  // scatter cursor starts at row base
    }
    if (i == 0) g_rowptr[NN] = EE;
}
__global__ void k_scatter(const int* __restrict__ src, const int* __restrict__ dst) {
    int e = blockIdx.x * blockDim.x + threadIdx.x;
    if (e >= EE) return;
    int s = src[e], d = dst[e];
    int pos = atomicAdd(&g_cursor[d], 1);
    float w = g_dinv[s] * g_dinv[d];
    g_csr[pos] = make_int2(s, __float_as_int(w));
}

// ---------------- weight split into fp16 hi/lo, transposed [n][k] ----------------
__global__ void k_cvt_w(const float* __restrict__ W1, const float* __restrict__ W2) {
    int i = blockIdx.x * blockDim.x + threadIdx.x;
    if (i >= NWELEM) return;
    float v;
    int oidx;
    if (i < FIN * HD) {
        int k = i / HD, n = i % HD;
        v = W1[i];
        oidx = n * FIN + k;
    } else {
        int j = i - FIN * HD;
        int l = j / (HD * HD), r = j % (HD * HD);
        int k = r / HD, n = r % HD;
        v = W2[j];
        oidx = FIN * HD + l * HD * HD + n * HD + k;
    }
    __half hi = __float2half_rn(v);
    float lof = v - __half2float(hi);
    g_WhiT[oidx] = hi;
    g_WloT[oidx] = __float2half_rn(lof);
}

// ---------------- fused layer: h_out = relu( agg(in) @ W + b ) ----------------
// Phase 1: warp-per-row CSR gather+aggregate (fp32), convert -> smem A (fp16)
// Phase 2: tensor-core GEMM (A exact fp16, W = hi + lo), bias+relu epilogue
#define MMA_F16(d, a0, a1, a2, a3, b0, b1)                                  \
    asm volatile("mma.sync.aligned.m16n8k16.row.col.f32.f16.f16.f32 "       \
                 "{%0,%1,%2,%3}, {%4,%5,%6,%7}, {%8,%9}, {%0,%1,%2,%3};"    \
                 : "+f"(d[0]), "+f"(d[1]), "+f"(d[2]), "+f"(d[3])           \
                 : "r"(a0), "r"(a1), "r"(a2), "r"(a3), "r"(b0), "r"(b1))

template <int K, bool FP32IN>
__global__ void __launch_bounds__(256, 2)
k_fused(const void* __restrict__ inp, const __half* __restrict__ BhiT,
        const __half* __restrict__ BloT, const float* __restrict__ bias,
        __half* __restrict__ Hout) {
    constexpr int AST = K + 8;
    extern __shared__ char sm[];
    __half* As  = (__half*)sm;
    __half* Bhi = (__half*)(sm + 128 * AST * 2);
    __half* Blo = Bhi + 128 * BST;

    int tid = threadIdx.x;
    int wid = tid >> 5, lane = tid & 31;
    int row0 = blockIdx.x * 128;

    // ---- Phase 1: gather + aggregate 16 rows per warp ----
    for (int rr = 0; rr < 16; rr++) {
        int r = wid * 16 + rr;
        int node = row0 + r;
        float a0 = 0.f, a1 = 0.f, a2 = 0.f, a3 = 0.f;
        if (node < NN) {
            float di = g_dinv[node];
            float ws = di * di;
            if constexpr (FP32IN) {
                float2 sv = ((const float2*)inp)[(size_t)node * 32 + lane];
                a0 = sv.x * ws; a1 = sv.y * ws;
            } else {
                uint2 sv = ((const uint2*)inp)[(size_t)node * 32 + lane];
                float2 f0 = __half22float2(*reinterpret_cast<__half2*>(&sv.x));
                float2 f1 = __half22float2(*reinterpret_cast<__half2*>(&sv.y));
                a0 = f0.x * ws; a1 = f0.y * ws; a2 = f1.x * ws; a3 = f1.y * ws;
            }
            int j = g_rowptr[node], end = g_rowptr[node + 1];
            for (; j + 1 < end; j += 2) {
                int2 e0 = g_csr[j], e1 = g_csr[j + 1];
                float w0 = __int_as_float(e0.y), w1 = __int_as_float(e1.y);
                if constexpr (FP32IN) {
                    float2 v0 = ((const float2*)inp)[(size_t)e0.x * 32 + lane];
                    float2 v1 = ((const float2*)inp)[(size_t)e1.x * 32 + lane];
                    a0 += v0.x * w0 + v1.x * w1;
                    a1 += v0.y * w0 + v1.y * w1;
                } else {
                    uint2 v0 = ((const uint2*)inp)[(size_t)e0.x * 32 + lane];
                    uint2 v1 = ((const uint2*)inp)[(size_t)e1.x * 32 + lane];
                    float2 u0 = __half22float2(*reinterpret_cast<__half2*>(&v0.x));
                    float2 u1 = __half22float2(*reinterpret_cast<__half2*>(&v0.y));
                    float2 u2 = __half22float2(*reinterpret_cast<__half2*>(&v1.x));
                    float2 u3 = __half22float2(*reinterpret_cast<__half2*>(&v1.y));
                    a0 += u0.x * w0 + u2.x * w1;
                    a1 += u0.y * w0 + u2.y * w1;
                    a2 += u1.x * w0 + u3.x * w1;
                    a3 += u1.y * w0 + u3.y * w1;
                }
            }
            if (j < end) {
                int2 e0 = g_csr[j];
                float w0 = __int_as_float(e0.y);
                if constexpr (FP32IN) {
                    float2 v0 = ((const float2*)inp)[(size_t)e0.x * 32 + lane];
                    a0 += v0.x * w0; a1 += v0.y * w0;
                } else {
                    uint2 v0 = ((const uint2*)inp)[(size_t)e0.x * 32 + lane];
                    float2 u0 = __half22float2(*reinterpret_cast<__half2*>(&v0.x));
                    float2 u1 = __half22float2(*reinterpret_cast<__half2*>(&v0.y));
                    a0 += u0.x * w0; a1 += u0.y * w0;
                    a2 += u1.x * w0; a3 += u1.y * w0;
                }
            }
        }
        if constexpr (FP32IN) {
            __half2 h0 = __floats2half2_rn(a0, a1);
            *(__half2*)&As[r * AST + lane * 2] = h0;
        } else {
            __half2 h0 = __floats2half2_rn(a0, a1);
            __half2 h1 = __floats2half2_rn(a2, a3);
            uint2 ov;
            ov.x = *reinterpret_cast<uint32_t*>(&h0);
            ov.y = *reinterpret_cast<uint32_t*>(&h1);
            *(uint2*)&As[r * AST + lane * 4] = ov;
        }
    }

    // ---- Phase 2: GEMM ----
    int wr = wid >> 1, wc = wid & 1;
    int mrow = wr * 32;
    int ncol = wc * 64;
    int lq = lane >> 2;
    int lr = lane & 3;

    float acc[2][8][4];
#pragma unroll
    for (int ma = 0; ma < 2; ma++)
#pragma unroll
        for (int na = 0; na < 8; na++)
#pragma unroll
            for (int r = 0; r < 4; r++) acc[ma][na][r] = 0.0f;

    for (int k0 = 0; k0 < K; k0 += 32) {
#pragma unroll
        for (int i = 0; i < 2; i++) {
            int li = tid + i * 256;
            int n = li >> 2;
            int c = (li & 3) * 8;
            *(uint4*)&Bhi[n * BST + c] = *(const uint4*)(BhiT + (size_t)n * K + k0 + c);
            *(uint4*)&Blo[n * BST + c] = *(const uint4*)(BloT + (size_t)n * K + k0 + c);
        }
        __syncthreads();
#pragma unroll
        for (int ks = 0; ks < 2; ks++) {
            int kk = k0 + ks * 16;   // global col in As
            int kl = ks * 16;        // local col in B smem
            uint32_t a[2][4];
#pragma unroll
            for (int ma = 0; ma < 2; ma++) {
                int rb = mrow + ma * 16;
                a[ma][0] = *(const uint32_t*)&As[(rb + lq) * AST + kk + 2 * lr];
                a[ma][1] = *(const uint32_t*)&As[(rb + lq + 8) * AST + kk + 2 * lr];
                a[ma][2] = *(const uint32_t*)&As[(rb + lq) * AST + kk + 2 * lr + 8];
                a[ma][3] = *(const uint32_t*)&As[(rb + lq + 8) * AST + kk + 2 * lr + 8];
            }
#pragma unroll
            for (int na = 0; na < 8; na++) {
                int n = ncol + na * 8 + lq;
                uint32_t bh0 = *(const uint32_t*)&Bhi[n * BST + kl + 2 * lr];
                uint32_t bh1 = *(const uint32_t*)&Bhi[n * BST + kl + 2 * lr + 8];
                uint32_t bl0 = *(const uint32_t*)&Blo[n * BST + kl + 2 * lr];
                uint32_t bl1 = *(const uint32_t*)&Blo[n * BST + kl + 2 * lr + 8];
#pragma unroll
                for (int ma = 0; ma < 2; ma++) {
                    MMA_F16(acc[ma][na], a[ma][0], a[ma][1], a[ma][2], a[ma][3], bh0, bh1);
                    MMA_F16(acc[ma][na], a[ma][0], a[ma][1], a[ma][2], a[ma][3], bl0, bl1);
                }
            }
        }
        __syncthreads();
    }

    // ---- epilogue: bias + relu, store fp16 h ----
#pragma unroll
    for (int ma = 0; ma < 2; ma++) {
        int r0 = row0 + mrow + ma * 16 + lq;
#pragma unroll
        for (int na = 0; na < 8; na++) {
            int col = ncol + na * 8 + 2 * lr;
            float bx = bias[col], by = bias[col + 1];
            float c0 = fmaxf(acc[ma][na][0] + bx, 0.f);
            float c1 = fmaxf(acc[ma][na][1] + by, 0.f);
            float c2 = fmaxf(acc[ma][na][2] + bx, 0.f);
            float c3 = fmaxf(acc[ma][na][3] + by, 0.f);
            if (r0 < NN)     *(__half2*)(Hout + (size_t)r0 * 128 + col) = __floats2half2_rn(c0, c1);
            if (r0 + 8 < NN) *(__half2*)(Hout + (size_t)(r0 + 8) * 128 + col) = __floats2half2_rn(c2, c3);
        }
    }
}

// ---------------- final layer: matvec (fp16 h, fp32 W3), then F=1 gather ----------------
__global__ void k_matvec(const __half* __restrict__ A, const float* __restrict__ W3,
                         float* __restrict__ out) {
    __shared__ float w[128];
    int tid = threadIdx.x;
    if (tid < 128) w[tid] = W3[tid];
    __syncthreads();
    int row = blockIdx.x * 8 + (tid >> 5);
    int lane = tid & 31;
    if (row >= NN) return;
    const __half* a = A + (size_t)row * 128;
    float s = __half2float(a[lane]) * w[lane]
            + __half2float(a[lane + 32]) * w[lane + 32]
            + __half2float(a[lane + 64]) * w[lane + 64]
            + __half2float(a[lane + 96]) * w[lane + 96];
#pragma unroll
    for (int off = 16; off > 0; off >>= 1) s += __shfl_down_sync(0xffffffffu, s, off);
    if (lane == 0) out[row] = s;
}

__global__ void k_final(const float* __restrict__ t, const float* __restrict__ b3,
                        float* __restrict__ out) {
    int i = blockIdx.x * blockDim.x + threadIdx.x;
    if (i >= NN) return;
    float di = g_dinv[i];
    float s = t[i] * di * di + b3[0];
    int j = g_rowptr[i], end = g_rowptr[i + 1];
    for (; j < end; j++) {
        int2 e = g_csr[j];
        s += t[e.x] * __int_as_float(e.y);
    }
    out[i] = s;
}

// ---------------- launch ----------------
extern "C" void kernel_launch(void* const* d_in, const int* in_sizes, int n_in,
                              void* d_out, int out_size) {
    const float* x  = (const float*)d_in[0];
    const int* ei   = (const int*)d_in[1];
    const float* W1 = (const float*)d_in[2];
    const float* b1 = (const float*)d_in[3];
    const float* W2 = (const float*)d_in[4];
    const float* b2 = (const float*)d_in[5];
    const float* W3 = (const float*)d_in[6];
    const float* b3 = (const float*)d_in[7];
    float* out = (float*)d_out;

    const int* src = ei;
    const int* dst = ei + EE;

    __half* h16;  cudaGetSymbolAddress((void**)&h16, g_h16);
    __half* h16b; cudaGetSymbolAddress((void**)&h16b, g_h16b);
    __half* whiT; cudaGetSymbolAddress((void**)&whiT, g_WhiT);
    __half* wloT; cudaGetSymbolAddress((void**)&wloT, g_WloT);
    float* tbuf;  cudaGetSymbolAddress((void**)&tbuf, g_t);

    constexpr int SMEM64  = 128 * (FIN + 8) * 2 + 2 * 128 * BST * 2;  // 38912
    constexpr int SMEM128 = 128 * (HD + 8) * 2 + 2 * 128 * BST * 2;   // 55296
    static bool attr_set = false;
    if (!attr_set) {
        cudaFuncSetAttribute(k_fused<FIN, true>,
                             cudaFuncAttributeMaxDynamicSharedMemorySize, SMEM64);
        cudaFuncSetAttribute(k_fused<HD, false>,
                             cudaFuncAttributeMaxDynamicSharedMemorySize, SMEM128);
        attr_set = true;
    }

    // CSR build + norm + weight split
    k_zero_cnt<<<(NN + 255) / 256, 256>>>();
    k_hist<<<(EE + 255) / 256, 256>>>(dst);
    k_cvt_w<<<(NWELEM + 255) / 256, 256>>>(W1, W2);
    k_dinv<<<(NN + 255) / 256, 256>>>();
    k_scan1<<<NSCAN, SCAN_BLK>>>();
    k_scan2<<<1, 128>>>();
    k_scan3<<<(NN + 255) / 256, 256>>>();
    k_scatter<<<(EE + 255) / 256, 256>>>(src, dst);

    const int GB = (NN + 127) / 128;

    // layer 1: h = relu(agg(x) @ W1 + b1), fused
    k_fused<FIN, true><<<GB, 256, SMEM64>>>(x, whiT, wloT, b1, h16);

    // hidden layers, ping-pong h buffers
    __half* cur = h16;
    __half* nxt = h16b;
    for (int l = 0; l < NLAYER; l++) {
        const __half* bh = whiT + FIN * HD + (size_t)l * HD * HD;
        const __half* bl = wloT + FIN * HD + (size_t)l * HD * HD;
        k_fused<HD, false><<<GB, 256, SMEM128>>>(cur, bh, bl, b2 + (size_t)l * HD, nxt);
        __half* tmp = cur; cur = nxt; nxt = tmp;
    }

    // final layer: matvec, then F=1 gather + b3
    k_matvec<<<(NN + 7) / 8, 256>>>(cur, W3, tbuf);
    k_final<<<(NN + 255) / 256, 256>>>(tbuf, b3, out);
}

// round 6
// speedup vs baseline: 1.8326x; 1.8326x over previous
#include <cuda_runtime.h>
#include <cuda_fp16.h>
#include <cstdint>

#define NN 100000
#define EE 1600000
#define HD 128
#define FIN 64
#define NLAYER 3
#define SCAN_BLK 1024
#define NSCAN ((NN + SCAN_BLK - 1) / SCAN_BLK)   // 98
#define NWELEM (FIN * HD + NLAYER * HD * HD)     // 57344
#define BST 40   // B smem stride (halves)
#define AST 40   // A smem stride (halves), tile k=32 + pad

// ---------------- device scratch ----------------
__device__ float  g_dinv[NN];
__device__ int    g_cnt[NN];
__device__ int    g_rowptr[NN + 1];
__device__ int    g_cursor[NN];
__device__ int    g_blocksum[NSCAN + 1];
__device__ int2   g_csr[EE];               // {src, weight-as-int}
__device__ float  g_t[NN];
__device__ __half g_x16[(size_t)NN * FIN];
__device__ __half g_a64[(size_t)NN * FIN];
__device__ __half g_h16[(size_t)NN * HD];
__device__ __half g_g16[(size_t)NN * HD];
__device__ __half g_WhiT[NWELEM];          // [n][k] fp16 hi
__device__ __half g_WloT[NWELEM];          // [n][k] fp16 lo

// ---------------- degree / norm / CSR build ----------------
__global__ void k_zero_cnt() {
    int i = blockIdx.x * blockDim.x + threadIdx.x;
    if (i < NN) g_cnt[i] = 0;
}
__global__ void k_hist(const int* __restrict__ dst) {
    int e = blockIdx.x * blockDim.x + threadIdx.x;
    if (e < EE) atomicAdd(&g_cnt[dst[e]], 1);
}
__global__ void k_scan1() {   // also computes dinv from cnt
    __shared__ int sh[SCAN_BLK];
    int i = blockIdx.x * SCAN_BLK + threadIdx.x;
    int v = (i < NN) ? g_cnt[i] : 0;
    if (i < NN) g_dinv[i] = rsqrtf((float)(v + 1));
    sh[threadIdx.x] = v;
    __syncthreads();
    int acc = v;
#pragma unroll
    for (int off = 1; off < SCAN_BLK; off <<= 1) {
        int t = (threadIdx.x >= off) ? sh[threadIdx.x - off] : 0;
        __syncthreads();
        acc += t;
        sh[threadIdx.x] = acc;
        __syncthreads();
    }
    if (i < NN) g_rowptr[i] = acc - v;
    if (threadIdx.x == SCAN_BLK - 1) g_blocksum[blockIdx.x] = acc;
}
__global__ void k_scan2() {
    __shared__ int sh[128];
    int i = threadIdx.x;
    int v = (i < NSCAN) ? g_blocksum[i] : 0;
    sh[i] = v;
    __syncthreads();
    int acc = v;
#pragma unroll
    for (int off = 1; off < 128; off <<= 1) {
        int t = (i >= off) ? sh[i - off] : 0;
        __syncthreads();
        acc += t;
        sh[i] = acc;
        __syncthreads();
    }
    if (i < NSCAN) g_blocksum[i] = acc - v;
}
__global__ void k_scan3() {
    int i = blockIdx.x * blockDim.x + threadIdx.x;
    if (i < NN) {
        int rp = g_rowptr[i] + g_blocksum[i / SCAN_BLK];
        g_rowptr[i] = rp;
        g_cursor[i] = rp;
    }
    if (i == 0) g_rowptr[NN] = EE;
}
__global__ void k_scatter(const int* __restrict__ src, const int* __restrict__ dst) {
    int e = blockIdx.x * blockDim.x + threadIdx.x;
    if (e >= EE) return;
    int s = src[e], d = dst[e];
    int pos = atomicAdd(&g_cursor[d], 1);
    float w = g_dinv[s] * g_dinv[d];
    g_csr[pos] = make_int2(s, __float_as_int(w));
}

// ---------------- conversions ----------------
__global__ void k_cvt_x(const float* __restrict__ x) {
    int i = blockIdx.x * blockDim.x + threadIdx.x;
    if (i < NN * FIN / 2) {
        float2 v = ((const float2*)x)[i];
        ((__half2*)g_x16)[i] = __floats2half2_rn(v.x, v.y);
    }
}
__global__ void k_cvt_w(const float* __restrict__ W1, const float* __restrict__ W2) {
    int i = blockIdx.x * blockDim.x + threadIdx.x;
    if (i >= NWELEM) return;
    float v;
    int oidx;
    if (i < FIN * HD) {
        int k = i / HD, n = i % HD;
        v = W1[i];
        oidx = n * FIN + k;
    } else {
        int j = i - FIN * HD;
        int l = j / (HD * HD), r = j % (HD * HD);
        int k = r / HD, n = r % HD;
        v = W2[j];
        oidx = FIN * HD + l * HD * HD + n * HD + k;
    }
    __half hi = __float2half_rn(v);
    float lof = v - __half2float(hi);
    g_WhiT[oidx] = hi;
    g_WloT[oidx] = __float2half_rn(lof);
}

// ---------------- gather aggregations (warp per node) ----------------
// F=64 fp16: lane owns 1 uint (2 halves), 128 B/row. No bias/relu.
__global__ void __launch_bounds__(256)
k_agg64(const __half* __restrict__ in, __half* __restrict__ out) {
    int node = blockIdx.x * 8 + (threadIdx.x >> 5);
    int lane = threadIdx.x & 31;
    if (node >= NN) return;
    const uint32_t* in1 = (const uint32_t*)in;
    float di = g_dinv[node];
    float w = di * di;
    uint32_t sv = in1[(size_t)node * 32 + lane];
    float2 f = __half22float2(*reinterpret_cast<__half2*>(&sv));
    float a0 = f.x * w, a1 = f.y * w;
    int j = g_rowptr[node], end = g_rowptr[node + 1];
    for (; j + 1 < end; j += 2) {
        int2 e0 = g_csr[j], e1 = g_csr[j + 1];
        float w0 = __int_as_float(e0.y), w1 = __int_as_float(e1.y);
        uint32_t v0 = in1[(size_t)e0.x * 32 + lane];
        uint32_t v1 = in1[(size_t)e1.x * 32 + lane];
        float2 u0 = __half22float2(*reinterpret_cast<__half2*>(&v0));
        float2 u1 = __half22float2(*reinterpret_cast<__half2*>(&v1));
        a0 += u0.x * w0 + u1.x * w1;
        a1 += u0.y * w0 + u1.y * w1;
    }
    if (j < end) {
        int2 e0 = g_csr[j];
        float w0 = __int_as_float(e0.y);
        uint32_t v0 = in1[(size_t)e0.x * 32 + lane];
        float2 u0 = __half22float2(*reinterpret_cast<__half2*>(&v0));
        a0 += u0.x * w0; a1 += u0.y * w0;
    }
    __half2 o = __floats2half2_rn(a0, a1);
    ((uint32_t*)out)[(size_t)node * 32 + lane] = *reinterpret_cast<uint32_t*>(&o);
}

// F=128 fp16: lane owns uint2 (4 halves), bias + relu fused.
__global__ void __launch_bounds__(256)
k_agg128(const __half* __restrict__ in, const float* __restrict__ bias,
         __half* __restrict__ out) {
    int node = blockIdx.x * 8 + (threadIdx.x >> 5);
    int lane = threadIdx.x & 31;
    if (node >= NN) return;
    const uint2* in2 = (const uint2*)in;
    float di = g_dinv[node];
    float w = di * di;
    uint2 sv = in2[(size_t)node * 32 + lane];
    float2 f0 = __half22float2(*reinterpret_cast<__half2*>(&sv.x));
    float2 f1 = __half22float2(*reinterpret_cast<__half2*>(&sv.y));
    float a0 = f0.x * w, a1 = f0.y * w, a2 = f1.x * w, a3 = f1.y * w;

    int j = g_rowptr[node], end = g_rowptr[node + 1];
    for (; j + 1 < end; j += 2) {
        int2 e0 = g_csr[j], e1 = g_csr[j + 1];
        float w0 = __int_as_float(e0.y), w1 = __int_as_float(e1.y);
        uint2 v0 = in2[(size_t)e0.x * 32 + lane];
        uint2 v1 = in2[(size_t)e1.x * 32 + lane];
        float2 u0 = __half22float2(*reinterpret_cast<__half2*>(&v0.x));
        float2 u1 = __half22float2(*reinterpret_cast<__half2*>(&v0.y));
        float2 u2 = __half22float2(*reinterpret_cast<__half2*>(&v1.x));
        float2 u3 = __half22float2(*reinterpret_cast<__half2*>(&v1.y));
        a0 += u0.x * w0 + u2.x * w1;
        a1 += u0.y * w0 + u2.y * w1;
        a2 += u1.x * w0 + u3.x * w1;
        a3 += u1.y * w0 + u3.y * w1;
    }
    if (j < end) {
        int2 e0 = g_csr[j];
        float w0 = __int_as_float(e0.y);
        uint2 v0 = in2[(size_t)e0.x * 32 + lane];
        float2 u0 = __half22float2(*reinterpret_cast<__half2*>(&v0.x));
        float2 u1 = __half22float2(*reinterpret_cast<__half2*>(&v0.y));
        a0 += u0.x * w0; a1 += u0.y * w0; a2 += u1.x * w0; a3 += u1.y * w0;
    }
    float4 b = *(const float4*)(bias + lane * 4);
    a0 = fmaxf(a0 + b.x, 0.f); a1 = fmaxf(a1 + b.y, 0.f);
    a2 = fmaxf(a2 + b.z, 0.f); a3 = fmaxf(a3 + b.w, 0.f);
    __half2 o0 = __floats2half2_rn(a0, a1);
    __half2 o1 = __floats2half2_rn(a2, a3);
    uint2 ov;
    ov.x = *reinterpret_cast<uint32_t*>(&o0);
    ov.y = *reinterpret_cast<uint32_t*>(&o1);
    ((uint2*)out)[(size_t)node * 32 + lane] = ov;
}

// ---------------- fp16 tensor-core GEMM: C[N,128] = A[N,K] @ W[K,128] ----------------
// A fp16 exact, B = Whi + Wlo (2 MMAs). Optional bias+relu epilogue.
#define MMA_F16(d, a0, a1, a2, a3, b0, b1)                                  \
    asm volatile("mma.sync.aligned.m16n8k16.row.col.f32.f16.f16.f32 "       \
                 "{%0,%1,%2,%3}, {%4,%5,%6,%7}, {%8,%9}, {%0,%1,%2,%3};"    \
                 : "+f"(d[0]), "+f"(d[1]), "+f"(d[2]), "+f"(d[3])           \
                 : "r"(a0), "r"(a1), "r"(a2), "r"(a3), "r"(b0), "r"(b1))

template <int K, bool BIASRELU>
__global__ void __launch_bounds__(256, 2)
k_gemm16(const __half* __restrict__ A, const __half* __restrict__ BhiT,
         const __half* __restrict__ BloT, const float* __restrict__ bias,
         __half* __restrict__ Cout) {
    __shared__ __half As[128 * AST];
    __shared__ __half Bhi[128 * BST];
    __shared__ __half Blo[128 * BST];

    int tid = threadIdx.x;
    int wid = tid >> 5, lane = tid & 31;
    int wr = wid >> 1, wc = wid & 1;
    int row0 = blockIdx.x * 128;
    int mrow = wr * 32;
    int ncol = wc * 64;
    int lq = lane >> 2;
    int lr = lane & 3;

    float acc[2][8][4];
#pragma unroll
    for (int ma = 0; ma < 2; ma++)
#pragma unroll
        for (int na = 0; na < 8; na++)
#pragma unroll
            for (int r = 0; r < 4; r++) acc[ma][na][r] = 0.0f;

    for (int k0 = 0; k0 < K; k0 += 32) {
#pragma unroll
        for (int i = 0; i < 2; i++) {
            int li = tid + i * 256;
            int r = li >> 2;
            int c = (li & 3) * 8;
            uint4 v = make_uint4(0, 0, 0, 0);
            int gr = row0 + r;
            if (gr < NN) v = *(const uint4*)(A + (size_t)gr * K + k0 + c);
            *(uint4*)&As[r * AST + c] = v;
        }
#pragma unroll
        for (int i = 0; i < 2; i++) {
            int li = tid + i * 256;
            int n = li >> 2;
            int c = (li & 3) * 8;
            *(uint4*)&Bhi[n * BST + c] = *(const uint4*)(BhiT + (size_t)n * K + k0 + c);
            *(uint4*)&Blo[n * BST + c] = *(const uint4*)(BloT + (size_t)n * K + k0 + c);
        }
        __syncthreads();
#pragma unroll
        for (int ks = 0; ks < 2; ks++) {
            int kk = ks * 16;
            uint32_t a[2][4];
#pragma unroll
            for (int ma = 0; ma < 2; ma++) {
                int rb = mrow + ma * 16;
                a[ma][0] = *(const uint32_t*)&As[(rb + lq) * AST + kk + 2 * lr];
                a[ma][1] = *(const uint32_t*)&As[(rb + lq + 8) * AST + kk + 2 * lr];
                a[ma][2] = *(const uint32_t*)&As[(rb + lq) * AST + kk + 2 * lr + 8];
                a[ma][3] = *(const uint32_t*)&As[(rb + lq + 8) * AST + kk + 2 * lr + 8];
            }
#pragma unroll
            for (int na = 0; na < 8; na++) {
                int n = ncol + na * 8 + lq;
                uint32_t bh0 = *(const uint32_t*)&Bhi[n * BST + kk + 2 * lr];
                uint32_t bh1 = *(const uint32_t*)&Bhi[n * BST + kk + 2 * lr + 8];
                uint32_t bl0 = *(const uint32_t*)&Blo[n * BST + kk + 2 * lr];
                uint32_t bl1 = *(const uint32_t*)&Blo[n * BST + kk + 2 * lr + 8];
#pragma unroll
                for (int ma = 0; ma < 2; ma++) {
                    MMA_F16(acc[ma][na], a[ma][0], a[ma][1], a[ma][2], a[ma][3], bh0, bh1);
                    MMA_F16(acc[ma][na], a[ma][0], a[ma][1], a[ma][2], a[ma][3], bl0, bl1);
                }
            }
        }
        __syncthreads();
    }
#pragma unroll
    for (int ma = 0; ma < 2; ma++) {
        int r0 = row0 + mrow + ma * 16 + lq;
#pragma unroll
        for (int na = 0; na < 8; na++) {
            int col = ncol + na * 8 + 2 * lr;
            float c0 = acc[ma][na][0], c1 = acc[ma][na][1];
            float c2 = acc[ma][na][2], c3 = acc[ma][na][3];
            if (BIASRELU) {
                float bx = bias[col], by = bias[col + 1];
                c0 = fmaxf(c0 + bx, 0.f); c1 = fmaxf(c1 + by, 0.f);
                c2 = fmaxf(c2 + bx, 0.f); c3 = fmaxf(c3 + by, 0.f);
            }
            if (r0 < NN)     *(__half2*)(Cout + (size_t)r0 * 128 + col) = __floats2half2_rn(c0, c1);
            if (r0 + 8 < NN) *(__half2*)(Cout + (size_t)(r0 + 8) * 128 + col) = __floats2half2_rn(c2, c3);
        }
    }
}

// ---------------- final layer: matvec (fp16 h, fp32 W3), then F=1 gather ----------------
__global__ void k_matvec(const __half* __restrict__ A, const float* __restrict__ W3,
                         float* __restrict__ out) {
    __shared__ float w[128];
    int tid = threadIdx.x;
    if (tid < 128) w[tid] = W3[tid];
    __syncthreads();
    int row = blockIdx.x * 8 + (tid >> 5);
    int lane = tid & 31;
    if (row >= NN) return;
    const __half* a = A + (size_t)row * 128;
    float s = __half2float(a[lane]) * w[lane]
            + __half2float(a[lane + 32]) * w[lane + 32]
            + __half2float(a[lane + 64]) * w[lane + 64]
            + __half2float(a[lane + 96]) * w[lane + 96];
#pragma unroll
    for (int off = 16; off > 0; off >>= 1) s += __shfl_down_sync(0xffffffffu, s, off);
    if (lane == 0) out[row] = s;
}

__global__ void k_final(const float* __restrict__ t, const float* __restrict__ b3,
                        float* __restrict__ out) {
    int i = blockIdx.x * blockDim.x + threadIdx.x;
    if (i >= NN) return;
    float di = g_dinv[i];
    float s = t[i] * di * di + b3[0];
    int j = g_rowptr[i], end = g_rowptr[i + 1];
    for (; j < end; j++) {
        int2 e = g_csr[j];
        s += t[e.x] * __int_as_float(e.y);
    }
    out[i] = s;
}

// ---------------- launch ----------------
extern "C" void kernel_launch(void* const* d_in, const int* in_sizes, int n_in,
                              void* d_out, int out_size) {
    const float* x  = (const float*)d_in[0];
    const int* ei   = (const int*)d_in[1];
    const float* W1 = (const float*)d_in[2];
    const float* b1 = (const float*)d_in[3];
    const float* W2 = (const float*)d_in[4];
    const float* b2 = (const float*)d_in[5];
    const float* W3 = (const float*)d_in[6];
    const float* b3 = (const float*)d_in[7];
    float* out = (float*)d_out;

    const int* src = ei;
    const int* dst = ei + EE;

    __half* x16;  cudaGetSymbolAddress((void**)&x16, g_x16);
    __half* a64;  cudaGetSymbolAddress((void**)&a64, g_a64);
    __half* h16;  cudaGetSymbolAddress((void**)&h16, g_h16);
    __half* g16;  cudaGetSymbolAddress((void**)&g16, g_g16);
    __half* whiT; cudaGetSymbolAddress((void**)&whiT, g_WhiT);
    __half* wloT; cudaGetSymbolAddress((void**)&wloT, g_WloT);
    float* tbuf;  cudaGetSymbolAddress((void**)&tbuf, g_t);

    // conversions (no deps) first
    k_cvt_w<<<(NWELEM + 255) / 256, 256>>>(W1, W2);
    k_cvt_x<<<(NN * FIN / 2 + 255) / 256, 256>>>(x);

    // CSR build + norm
    k_zero_cnt<<<(NN + 255) / 256, 256>>>();
    k_hist<<<(EE + 255) / 256, 256>>>(dst);
    k_scan1<<<NSCAN, SCAN_BLK>>>();
    k_scan2<<<1, 128>>>();
    k_scan3<<<(NN + 255) / 256, 256>>>();
    k_scatter<<<(EE + 255) / 256, 256>>>(src, dst);

    const int GB = (NN + 127) / 128;

    // layer 1: agg-first at F=64 fp16, then GEMM 64->128 with b1+relu
    k_agg64<<<(NN + 7) / 8, 256>>>(x16, a64);
    k_gemm16<FIN, true><<<GB, 256>>>(a64, whiT, wloT, b1, h16);

    // hidden layers: GEMM (no bias) then agg128 (bias+relu)
    for (int l = 0; l < NLAYER; l++) {
        const __half* bh = whiT + FIN * HD + (size_t)l * HD * HD;
        const __half* bl = wloT + FIN * HD + (size_t)l * HD * HD;
        k_gemm16<HD, false><<<GB, 256>>>(h16, bh, bl, nullptr, g16);
        k_agg128<<<(NN + 7) / 8, 256>>>(g16, b2 + (size_t)l * HD, h16);
    }

    // final layer: matvec, then F=1 gather + b3
    k_matvec<<<(NN + 7) / 8, 256>>>(h16, W3, tbuf);
    k_final<<<(NN + 255) / 256, 256>>>(tbuf, b3, out);
}

// round 7
// speedup vs baseline: 1.9135x; 1.0441x over previous
#include <cuda_runtime.h>
#include <cuda_fp16.h>
#include <cstdint>

#define NN 100000
#define EE 1600000
#define HD 128
#define FIN 64
#define NLAYER 3
#define SCAN_BLK 1024
#define NSCAN ((NN + SCAN_BLK - 1) / SCAN_BLK)   // 98
#define NWELEM (FIN * HD + NLAYER * HD * HD)     // 57344
#define BST 40   // B smem stride (halves)
#define AST 40   // A smem stride (halves)
#define XHALF (NN * FIN / 2)                     // 3.2M half2 elements

// ---------------- device scratch ----------------
__device__ float  g_dinv[NN];
__device__ int    g_cnt[NN];
__device__ int    g_rowptr[NN + 1];
__device__ int    g_cursor[NN];
__device__ int    g_blocksum[NSCAN + 1];
__device__ int2   g_csr[EE];               // {src, weight-as-int}
__device__ float  g_t[NN];
__device__ __half g_x16[(size_t)NN * FIN];
__device__ __half g_a64[(size_t)NN * FIN];
__device__ __half g_h16[(size_t)NN * HD];
__device__ __half g_g16[(size_t)NN * HD];
__device__ __half g_WhiT[NWELEM];          // [n][k] fp16 hi
__device__ __half g_WloT[NWELEM];          // [n][k] fp16 lo

// ---------------- prep: zero cnt + weight split + x convert (one kernel) ----------------
__global__ void k_prep(const float* __restrict__ x, const float* __restrict__ W1,
                       const float* __restrict__ W2) {
    int i = blockIdx.x * blockDim.x + threadIdx.x;
    if (i < XHALF) {
        float2 v = ((const float2*)x)[i];
        ((__half2*)g_x16)[i] = __floats2half2_rn(v.x, v.y);
    }
    if (i < NN) g_cnt[i] = 0;
    if (i < NWELEM) {
        float v;
        int oidx;
        if (i < FIN * HD) {
            int k = i / HD, n = i % HD;
            v = W1[i];
            oidx = n * FIN + k;
        } else {
            int j = i - FIN * HD;
            int l = j / (HD * HD), r = j % (HD * HD);
            int k = r / HD, n = r % HD;
            v = W2[j];
            oidx = FIN * HD + l * HD * HD + n * HD + k;
        }
        __half hi = __float2half_rn(v);
        float lof = v - __half2float(hi);
        g_WhiT[oidx] = hi;
        g_WloT[oidx] = __float2half_rn(lof);
    }
}

// ---------------- degree / norm / CSR build ----------------
__global__ void k_hist(const int* __restrict__ dst) {
    int t = blockIdx.x * blockDim.x + threadIdx.x;
    int e = t * 4;
    if (e + 3 < EE) {
        int4 d = *(const int4*)(dst + e);
        atomicAdd(&g_cnt[d.x], 1);
        atomicAdd(&g_cnt[d.y], 1);
        atomicAdd(&g_cnt[d.z], 1);
        atomicAdd(&g_cnt[d.w], 1);
    } else {
        for (int k = e; k < EE; k++) atomicAdd(&g_cnt[dst[k]], 1);
    }
}
__global__ void k_scan1() {   // also computes dinv
    __shared__ int sh[SCAN_BLK];
    int i = blockIdx.x * SCAN_BLK + threadIdx.x;
    int v = (i < NN) ? g_cnt[i] : 0;
    if (i < NN) g_dinv[i] = rsqrtf((float)(v + 1));
    sh[threadIdx.x] = v;
    __syncthreads();
    int acc = v;
#pragma unroll
    for (int off = 1; off < SCAN_BLK; off <<= 1) {
        int t = (threadIdx.x >= off) ? sh[threadIdx.x - off] : 0;
        __syncthreads();
        acc += t;
        sh[threadIdx.x] = acc;
        __syncthreads();
    }
    if (i < NN) g_rowptr[i] = acc - v;
    if (threadIdx.x == SCAN_BLK - 1) g_blocksum[blockIdx.x] = acc;
}
__global__ void k_scan2() {
    __shared__ int sh[128];
    int i = threadIdx.x;
    int v = (i < NSCAN) ? g_blocksum[i] : 0;
    sh[i] = v;
    __syncthreads();
    int acc = v;
#pragma unroll
    for (int off = 1; off < 128; off <<= 1) {
        int t = (i >= off) ? sh[i - off] : 0;
        __syncthreads();
        acc += t;
        sh[i] = acc;
        __syncthreads();
    }
    if (i < NSCAN) g_blocksum[i] = acc - v;
}
__global__ void k_scan3() {
    int i = blockIdx.x * blockDim.x + threadIdx.x;
    if (i < NN) {
        int rp = g_rowptr[i] + g_blocksum[i / SCAN_BLK];
        g_rowptr[i] = rp;
        g_cursor[i] = rp;
    }
    if (i == 0) g_rowptr[NN] = EE;
}
__global__ void k_scatter(const int* __restrict__ src, const int* __restrict__ dst) {
    int t = blockIdx.x * blockDim.x + threadIdx.x;
    int e = t * 4;
    if (e + 3 < EE) {
        int4 s4 = *(const int4*)(src + e);
        int4 d4 = *(const int4*)(dst + e);
#pragma unroll
        for (int k = 0; k < 4; k++) {
            int s = (&s4.x)[k], d = (&d4.x)[k];
            int pos = atomicAdd(&g_cursor[d], 1);
            float w = g_dinv[s] * g_dinv[d];
            g_csr[pos] = make_int2(s, __float_as_int(w));
        }
    } else {
        for (int k = e; k < EE; k++) {
            int s = src[k], d = dst[k];
            int pos = atomicAdd(&g_cursor[d], 1);
            float w = g_dinv[s] * g_dinv[d];
            g_csr[pos] = make_int2(s, __float_as_int(w));
        }
    }
}

// ---------------- gather aggregations (warp per node) ----------------
// F=64 fp16 (layer-1 pre-aggregation of x)
__global__ void __launch_bounds__(256)
k_agg64(const __half* __restrict__ in, __half* __restrict__ out) {
    int node = blockIdx.x * 8 + (threadIdx.x >> 5);
    int lane = threadIdx.x & 31;
    if (node >= NN) return;
    const uint32_t* in1 = (const uint32_t*)in;
    float di = g_dinv[node];
    float w = di * di;
    uint32_t sv = in1[(size_t)node * 32 + lane];
    float2 f = __half22float2(*reinterpret_cast<__half2*>(&sv));
    float a0 = f.x * w, a1 = f.y * w;
    int j = g_rowptr[node], end = g_rowptr[node + 1];
    for (; j + 1 < end; j += 2) {
        int2 e0 = g_csr[j], e1 = g_csr[j + 1];
        float w0 = __int_as_float(e0.y), w1 = __int_as_float(e1.y);
        uint32_t v0 = in1[(size_t)e0.x * 32 + lane];
        uint32_t v1 = in1[(size_t)e1.x * 32 + lane];
        float2 u0 = __half22float2(*reinterpret_cast<__half2*>(&v0));
        float2 u1 = __half22float2(*reinterpret_cast<__half2*>(&v1));
        a0 += u0.x * w0 + u1.x * w1;
        a1 += u0.y * w0 + u1.y * w1;
    }
    if (j < end) {
        int2 e0 = g_csr[j];
        float w0 = __int_as_float(e0.y);
        uint32_t v0 = in1[(size_t)e0.x * 32 + lane];
        float2 u0 = __half22float2(*reinterpret_cast<__half2*>(&v0));
        a0 += u0.x * w0; a1 += u0.y * w0;
    }
    __half2 o = __floats2half2_rn(a0, a1);
    ((uint32_t*)out)[(size_t)node * 32 + lane] = *reinterpret_cast<uint32_t*>(&o);
}

// F=128 fp16, bias+relu fused. LAST variant also fuses the 128->1 matvec (W3),
// writing t[node] instead of h.
template <bool LAST>
__global__ void __launch_bounds__(256)
k_agg128(const __half* __restrict__ in, const float* __restrict__ bias,
         __half* __restrict__ out, const float* __restrict__ W3,
         float* __restrict__ tout) {
    int node = blockIdx.x * 8 + (threadIdx.x >> 5);
    int lane = threadIdx.x & 31;
    if (node >= NN) return;
    const uint2* in2 = (const uint2*)in;
    float di = g_dinv[node];
    float w = di * di;
    uint2 sv = in2[(size_t)node * 32 + lane];
    float2 f0 = __half22float2(*reinterpret_cast<__half2*>(&sv.x));
    float2 f1 = __half22float2(*reinterpret_cast<__half2*>(&sv.y));
    float a0 = f0.x * w, a1 = f0.y * w, a2 = f1.x * w, a3 = f1.y * w;

    int j = g_rowptr[node], end = g_rowptr[node + 1];
    for (; j + 1 < end; j += 2) {
        int2 e0 = g_csr[j], e1 = g_csr[j + 1];
        float w0 = __int_as_float(e0.y), w1 = __int_as_float(e1.y);
        uint2 v0 = in2[(size_t)e0.x * 32 + lane];
        uint2 v1 = in2[(size_t)e1.x * 32 + lane];
        float2 u0 = __half22float2(*reinterpret_cast<__half2*>(&v0.x));
        float2 u1 = __half22float2(*reinterpret_cast<__half2*>(&v0.y));
        float2 u2 = __half22float2(*reinterpret_cast<__half2*>(&v1.x));
        float2 u3 = __half22float2(*reinterpret_cast<__half2*>(&v1.y));
        a0 += u0.x * w0 + u2.x * w1;
        a1 += u0.y * w0 + u2.y * w1;
        a2 += u1.x * w0 + u3.x * w1;
        a3 += u1.y * w0 + u3.y * w1;
    }
    if (j < end) {
        int2 e0 = g_csr[j];
        float w0 = __int_as_float(e0.y);
        uint2 v0 = in2[(size_t)e0.x * 32 + lane];
        float2 u0 = __half22float2(*reinterpret_cast<__half2*>(&v0.x));
        float2 u1 = __half22float2(*reinterpret_cast<__half2*>(&v0.y));
        a0 += u0.x * w0; a1 += u0.y * w0; a2 += u1.x * w0; a3 += u1.y * w0;
    }
    float4 b = *(const float4*)(bias + lane * 4);
    a0 = fmaxf(a0 + b.x, 0.f); a1 = fmaxf(a1 + b.y, 0.f);
    a2 = fmaxf(a2 + b.z, 0.f); a3 = fmaxf(a3 + b.w, 0.f);
    if (LAST) {
        float4 w3 = *(const float4*)(W3 + lane * 4);
        float s = a0 * w3.x + a1 * w3.y + a2 * w3.z + a3 * w3.w;
#pragma unroll
        for (int off = 16; off > 0; off >>= 1) s += __shfl_xor_sync(0xffffffffu, s, off);
        if (lane == 0) tout[node] = s;
    } else {
        __half2 o0 = __floats2half2_rn(a0, a1);
        __half2 o1 = __floats2half2_rn(a2, a3);
        uint2 ov;
        ov.x = *reinterpret_cast<uint32_t*>(&o0);
        ov.y = *reinterpret_cast<uint32_t*>(&o1);
        ((uint2*)out)[(size_t)node * 32 + lane] = ov;
    }
}

// ---------------- fp16 tensor-core GEMM: C[N,128] = A[N,K] @ W[K,128] ----------------
#define MMA_F16(d, a0, a1, a2, a3, b0, b1)                                  \
    asm volatile("mma.sync.aligned.m16n8k16.row.col.f32.f16.f16.f32 "       \
                 "{%0,%1,%2,%3}, {%4,%5,%6,%7}, {%8,%9}, {%0,%1,%2,%3};"    \
                 : "+f"(d[0]), "+f"(d[1]), "+f"(d[2]), "+f"(d[3])           \
                 : "r"(a0), "r"(a1), "r"(a2), "r"(a3), "r"(b0), "r"(b1))

template <int K, bool BIASRELU>
__global__ void __launch_bounds__(256, 2)
k_gemm16(const __half* __restrict__ A, const __half* __restrict__ BhiT,
         const __half* __restrict__ BloT, const float* __restrict__ bias,
         __half* __restrict__ Cout) {
    __shared__ __half As[128 * AST];
    __shared__ __half Bhi[128 * BST];
    __shared__ __half Blo[128 * BST];

    int tid = threadIdx.x;
    int wid = tid >> 5, lane = tid & 31;
    int wr = wid >> 1, wc = wid & 1;
    int row0 = blockIdx.x * 128;
    int mrow = wr * 32;
    int ncol = wc * 64;
    int lq = lane >> 2;
    int lr = lane & 3;

    float acc[2][8][4];
#pragma unroll
    for (int ma = 0; ma < 2; ma++)
#pragma unroll
        for (int na = 0; na < 8; na++)
#pragma unroll
            for (int r = 0; r < 4; r++) acc[ma][na][r] = 0.0f;

    for (int k0 = 0; k0 < K; k0 += 32) {
#pragma unroll
        for (int i = 0; i < 2; i++) {
            int li = tid + i * 256;
            int r = li >> 2;
            int c = (li & 3) * 8;
            uint4 v = make_uint4(0, 0, 0, 0);
            int gr = row0 + r;
            if (gr < NN) v = *(const uint4*)(A + (size_t)gr * K + k0 + c);
            *(uint4*)&As[r * AST + c] = v;
        }
#pragma unroll
        for (int i = 0; i < 2; i++) {
            int li = tid + i * 256;
            int n = li >> 2;
            int c = (li & 3) * 8;
            *(uint4*)&Bhi[n * BST + c] = *(const uint4*)(BhiT + (size_t)n * K + k0 + c);
            *(uint4*)&Blo[n * BST + c] = *(const uint4*)(BloT + (size_t)n * K + k0 + c);
        }
        __syncthreads();
#pragma unroll
        for (int ks = 0; ks < 2; ks++) {
            int kk = ks * 16;
            uint32_t a[2][4];
#pragma unroll
            for (int ma = 0; ma < 2; ma++) {
                int rb = mrow + ma * 16;
                a[ma][0] = *(const uint32_t*)&As[(rb + lq) * AST + kk + 2 * lr];
                a[ma][1] = *(const uint32_t*)&As[(rb + lq + 8) * AST + kk + 2 * lr];
                a[ma][2] = *(const uint32_t*)&As[(rb + lq) * AST + kk + 2 * lr + 8];
                a[ma][3] = *(const uint32_t*)&As[(rb + lq + 8) * AST + kk + 2 * lr + 8];
            }
#pragma unroll
            for (int na = 0; na < 8; na++) {
                int n = ncol + na * 8 + lq;
                uint32_t bh0 = *(const uint32_t*)&Bhi[n * BST + kk + 2 * lr];
                uint32_t bh1 = *(const uint32_t*)&Bhi[n * BST + kk + 2 * lr + 8];
                uint32_t bl0 = *(const uint32_t*)&Blo[n * BST + kk + 2 * lr];
                uint32_t bl1 = *(const uint32_t*)&Blo[n * BST + kk + 2 * lr + 8];
#pragma unroll
                for (int ma = 0; ma < 2; ma++) {
                    MMA_F16(acc[ma][na], a[ma][0], a[ma][1], a[ma][2], a[ma][3], bh0, bh1);
                    MMA_F16(acc[ma][na], a[ma][0], a[ma][1], a[ma][2], a[ma][3], bl0, bl1);
                }
            }
        }
        __syncthreads();
    }
#pragma unroll
    for (int ma = 0; ma < 2; ma++) {
        int r0 = row0 + mrow + ma * 16 + lq;
#pragma unroll
        for (int na = 0; na < 8; na++) {
            int col = ncol + na * 8 + 2 * lr;
            float c0 = acc[ma][na][0], c1 = acc[ma][na][1];
            float c2 = acc[ma][na][2], c3 = acc[ma][na][3];
            if (BIASRELU) {
                float bx = bias[col], by = bias[col + 1];
                c0 = fmaxf(c0 + bx, 0.f); c1 = fmaxf(c1 + by, 0.f);
                c2 = fmaxf(c2 + bx, 0.f); c3 = fmaxf(c3 + by, 0.f);
            }
            if (r0 < NN)     *(__half2*)(Cout + (size_t)r0 * 128 + col) = __floats2half2_rn(c0, c1);
            if (r0 + 8 < NN) *(__half2*)(Cout + (size_t)(r0 + 8) * 128 + col) = __floats2half2_rn(c2, c3);
        }
    }
}

// ---------------- output: F=1 gather ----------------
__global__ void k_final(const float* __restrict__ t, const float* __restrict__ b3,
                        float* __restrict__ out) {
    int i = blockIdx.x * blockDim.x + threadIdx.x;
    if (i >= NN) return;
    float di = g_dinv[i];
    float s = t[i] * di * di + b3[0];
    int j = g_rowptr[i], end = g_rowptr[i + 1];
    for (; j < end; j++) {
        int2 e = g_csr[j];
        s += t[e.x] * __int_as_float(e.y);
    }
    out[i] = s;
}

// ---------------- launch ----------------
extern "C" void kernel_launch(void* const* d_in, const int* in_sizes, int n_in,
                              void* d_out, int out_size) {
    const float* x  = (const float*)d_in[0];
    const int* ei   = (const int*)d_in[1];
    const float* W1 = (const float*)d_in[2];
    const float* b1 = (const float*)d_in[3];
    const float* W2 = (const float*)d_in[4];
    const float* b2 = (const float*)d_in[5];
    const float* W3 = (const float*)d_in[6];
    const float* b3 = (const float*)d_in[7];
    float* out = (float*)d_out;

    const int* src = ei;
    const int* dst = ei + EE;

    __half* x16;  cudaGetSymbolAddress((void**)&x16, g_x16);
    __half* a64;  cudaGetSymbolAddress((void**)&a64, g_a64);
    __half* h16;  cudaGetSymbolAddress((void**)&h16, g_h16);
    __half* g16;  cudaGetSymbolAddress((void**)&g16, g_g16);
    __half* whiT; cudaGetSymbolAddress((void**)&whiT, g_WhiT);
    __half* wloT; cudaGetSymbolAddress((void**)&wloT, g_WloT);
    float* tbuf;  cudaGetSymbolAddress((void**)&tbuf, g_t);

    // prep (x convert + weight split + cnt zero) — one launch
    k_prep<<<(XHALF + 255) / 256, 256>>>(x, W1, W2);

    // CSR build + norm
    k_hist<<<(EE / 4 + 255) / 256, 256>>>(dst);
    k_scan1<<<NSCAN, SCAN_BLK>>>();
    k_scan2<<<1, 128>>>();
    k_scan3<<<(NN + 255) / 256, 256>>>();
    k_scatter<<<(EE / 4 + 255) / 256, 256>>>(src, dst);

    const int GB = (NN + 127) / 128;

    // layer 1: agg-first at F=64 fp16, then GEMM 64->128 with b1+relu
    k_agg64<<<(NN + 7) / 8, 256>>>(x16, a64);
    k_gemm16<FIN, true><<<GB, 256>>>(a64, whiT, wloT, b1, h16);

    // hidden layers: GEMM (no bias) then agg128 (bias+relu); last agg fuses matvec
    for (int l = 0; l < NLAYER; l++) {
        const __half* bh = whiT + FIN * HD + (size_t)l * HD * HD;
        const __half* bl = wloT + FIN * HD + (size_t)l * HD * HD;
        k_gemm16<HD, false><<<GB, 256>>>(h16, bh, bl, nullptr, g16);
        if (l < NLAYER - 1)
            k_agg128<false><<<(NN + 7) / 8, 256>>>(g16, b2 + (size_t)l * HD,
                                                   h16, nullptr, nullptr);
        else
            k_agg128<true><<<(NN + 7) / 8, 256>>>(g16, b2 + (size_t)l * HD,
                                                  nullptr, W3, tbuf);
    }

    // output: F=1 gather + b3
    k_final<<<(NN + 255) / 256, 256>>>(tbuf, b3, out);
}

// round 8
// speedup vs baseline: 1.9233x; 1.0051x over previous
#include <cuda_runtime.h>
#include <cuda_fp16.h>
#include <cstdint>

#define NN 100000
#define EE 1600000
#define HD 128
#define FIN 64
#define NLAYER 3
#define SCAN_BLK 1024
#define NSCAN ((NN + SCAN_BLK - 1) / SCAN_BLK)   // 98
#define NWELEM (FIN * HD + NLAYER * HD * HD)     // 57344
#define BST 40   // B smem stride (halves)
#define AST 40   // A smem stride (halves)
#define XQUAD (NN * FIN / 4)                     // 1.6M float4 elements

// ---------------- device scratch ----------------
__device__ float  g_dinv[NN];
__device__ int    g_cnt[NN + 1];           // [NN] = scan done-counter
__device__ int    g_rowptr[NN + 1];
__device__ int    g_cursor[NN];
__device__ int    g_blocksum[NSCAN + 1];
__device__ int2   g_csr[EE];               // {src, weight-as-int}
__device__ float  g_t[NN];
__device__ __half g_x16[(size_t)NN * FIN];
__device__ __half g_a64[(size_t)NN * FIN];
__device__ __half g_h16[(size_t)NN * HD];
__device__ __half g_g16[(size_t)NN * HD];
__device__ __half g_WhiT[NWELEM];          // [n][k] fp16 hi
__device__ __half g_WloT[NWELEM];          // [n][k] fp16 lo

// ---------------- prep: weight split + x convert ----------------
__global__ void k_prep(const float* __restrict__ x, const float* __restrict__ W1,
                       const float* __restrict__ W2) {
    int i = blockIdx.x * blockDim.x + threadIdx.x;
    if (i < XQUAD) {
        float4 v = ((const float4*)x)[i];
        __half2 h0 = __floats2half2_rn(v.x, v.y);
        __half2 h1 = __floats2half2_rn(v.z, v.w);
        uint2 o;
        o.x = *reinterpret_cast<uint32_t*>(&h0);
        o.y = *reinterpret_cast<uint32_t*>(&h1);
        ((uint2*)g_x16)[i] = o;
    }
    if (i < NWELEM) {
        float v;
        int oidx;
        if (i < FIN * HD) {
            int k = i / HD, n = i % HD;
            v = W1[i];
            oidx = n * FIN + k;
        } else {
            int j = i - FIN * HD;
            int l = j / (HD * HD), r = j % (HD * HD);
            int k = r / HD, n = r % HD;
            v = W2[j];
            oidx = FIN * HD + l * HD * HD + n * HD + k;
        }
        __half hi = __float2half_rn(v);
        float lof = v - __half2float(hi);
        g_WhiT[oidx] = hi;
        g_WloT[oidx] = __float2half_rn(lof);
    }
}

// ---------------- degree / norm / CSR build ----------------
__global__ void k_hist(const int* __restrict__ dst) {
    int t = blockIdx.x * blockDim.x + threadIdx.x;
    int e = t * 4;
    if (e + 3 < EE) {
        int4 d = *(const int4*)(dst + e);
        atomicAdd(&g_cnt[d.x], 1);
        atomicAdd(&g_cnt[d.y], 1);
        atomicAdd(&g_cnt[d.z], 1);
        atomicAdd(&g_cnt[d.w], 1);
    } else {
        for (int k = e; k < EE; k++) atomicAdd(&g_cnt[dst[k]], 1);
    }
}
// scan1: block-local scan + dinv; LAST block (fence+counter) scans block sums in place
__global__ void k_scan1() {
    __shared__ int sh[SCAN_BLK];
    __shared__ int s_last;
    int i = blockIdx.x * SCAN_BLK + threadIdx.x;
    int v = (i < NN) ? g_cnt[i] : 0;
    if (i < NN) g_dinv[i] = rsqrtf((float)(v + 1));
    sh[threadIdx.x] = v;
    __syncthreads();
    int acc = v;
#pragma unroll
    for (int off = 1; off < SCAN_BLK; off <<= 1) {
        int t = (threadIdx.x >= off) ? sh[threadIdx.x - off] : 0;
        __syncthreads();
        acc += t;
        sh[threadIdx.x] = acc;
        __syncthreads();
    }
    if (i < NN) g_rowptr[i] = acc - v;
    if (threadIdx.x == SCAN_BLK - 1) g_blocksum[blockIdx.x] = acc;
    __threadfence();
    __syncthreads();
    if (threadIdx.x == 0) {
        int d = atomicAdd(&g_cnt[NN], 1);
        s_last = (d == NSCAN - 1);
    }
    __syncthreads();
    if (s_last) {   // uniform across block
        int j = threadIdx.x;
        int bv = (j < NSCAN) ? g_blocksum[j] : 0;
        sh[threadIdx.x] = bv;
        __syncthreads();
        int bacc = bv;
#pragma unroll
        for (int off = 1; off < 128; off <<= 1) {
            int tt = (j >= off && j < 128) ? sh[j - off] : 0;
            __syncthreads();
            if (j < 128) { bacc += tt; sh[j] = bacc; }
            __syncthreads();
        }
        if (j < NSCAN) g_blocksum[j] = bacc - bv;   // exclusive
    }
}
__global__ void k_scan3() {
    int i = blockIdx.x * blockDim.x + threadIdx.x;
    if (i < NN) {
        int rp = g_rowptr[i] + g_blocksum[i / SCAN_BLK];
        g_rowptr[i] = rp;
        g_cursor[i] = rp;
    }
    if (i == 0) g_rowptr[NN] = EE;
}
__global__ void k_scatter(const int* __restrict__ src, const int* __restrict__ dst) {
    int t = blockIdx.x * blockDim.x + threadIdx.x;
    int e = t * 4;
    if (e + 3 < EE) {
        int4 s4 = *(const int4*)(src + e);
        int4 d4 = *(const int4*)(dst + e);
#pragma unroll
        for (int k = 0; k < 4; k++) {
            int s = (&s4.x)[k], d = (&d4.x)[k];
            int pos = atomicAdd(&g_cursor[d], 1);
            float w = g_dinv[s] * g_dinv[d];
            g_csr[pos] = make_int2(s, __float_as_int(w));
        }
    } else {
        for (int k = e; k < EE; k++) {
            int s = src[k], d = dst[k];
            int pos = atomicAdd(&g_cursor[d], 1);
            float w = g_dinv[s] * g_dinv[d];
            g_csr[pos] = make_int2(s, __float_as_int(w));
        }
    }
}

// ---------------- gather aggregations (warp per node) ----------------
__global__ void __launch_bounds__(256)
k_agg64(const __half* __restrict__ in, __half* __restrict__ out) {
    int node = blockIdx.x * 8 + (threadIdx.x >> 5);
    int lane = threadIdx.x & 31;
    if (node >= NN) return;
    const uint32_t* in1 = (const uint32_t*)in;
    float di = g_dinv[node];
    float w = di * di;
    uint32_t sv = in1[(size_t)node * 32 + lane];
    float2 f = __half22float2(*reinterpret_cast<__half2*>(&sv));
    float a0 = f.x * w, a1 = f.y * w;
    int j = g_rowptr[node], end = g_rowptr[node + 1];
    for (; j + 1 < end; j += 2) {
        int2 e0 = g_csr[j], e1 = g_csr[j + 1];
        float w0 = __int_as_float(e0.y), w1 = __int_as_float(e1.y);
        uint32_t v0 = in1[(size_t)e0.x * 32 + lane];
        uint32_t v1 = in1[(size_t)e1.x * 32 + lane];
        float2 u0 = __half22float2(*reinterpret_cast<__half2*>(&v0));
        float2 u1 = __half22float2(*reinterpret_cast<__half2*>(&v1));
        a0 += u0.x * w0 + u1.x * w1;
        a1 += u0.y * w0 + u1.y * w1;
    }
    if (j < end) {
        int2 e0 = g_csr[j];
        float w0 = __int_as_float(e0.y);
        uint32_t v0 = in1[(size_t)e0.x * 32 + lane];
        float2 u0 = __half22float2(*reinterpret_cast<__half2*>(&v0));
        a0 += u0.x * w0; a1 += u0.y * w0;
    }
    __half2 o = __floats2half2_rn(a0, a1);
    ((uint32_t*)out)[(size_t)node * 32 + lane] = *reinterpret_cast<uint32_t*>(&o);
}

template <bool LAST>
__global__ void __launch_bounds__(256)
k_agg128(const __half* __restrict__ in, const float* __restrict__ bias,
         __half* __restrict__ out, const float* __restrict__ W3,
         float* __restrict__ tout) {
    int node = blockIdx.x * 8 + (threadIdx.x >> 5);
    int lane = threadIdx.x & 31;
    if (node >= NN) return;
    const uint2* in2 = (const uint2*)in;
    float di = g_dinv[node];
    float w = di * di;
    uint2 sv = in2[(size_t)node * 32 + lane];
    float2 f0 = __half22float2(*reinterpret_cast<__half2*>(&sv.x));
    float2 f1 = __half22float2(*reinterpret_cast<__half2*>(&sv.y));
    float a0 = f0.x * w, a1 = f0.y * w, a2 = f1.x * w, a3 = f1.y * w;

    int j = g_rowptr[node], end = g_rowptr[node + 1];
    for (; j + 1 < end; j += 2) {
        int2 e0 = g_csr[j], e1 = g_csr[j + 1];
        float w0 = __int_as_float(e0.y), w1 = __int_as_float(e1.y);
        uint2 v0 = in2[(size_t)e0.x * 32 + lane];
        uint2 v1 = in2[(size_t)e1.x * 32 + lane];
        float2 u0 = __half22float2(*reinterpret_cast<__half2*>(&v0.x));
        float2 u1 = __half22float2(*reinterpret_cast<__half2*>(&v0.y));
        float2 u2 = __half22float2(*reinterpret_cast<__half2*>(&v1.x));
        float2 u3 = __half22float2(*reinterpret_cast<__half2*>(&v1.y));
        a0 += u0.x * w0 + u2.x * w1;
        a1 += u0.y * w0 + u2.y * w1;
        a2 += u1.x * w0 + u3.x * w1;
        a3 += u1.y * w0 + u3.y * w1;
    }
    if (j < end) {
        int2 e0 = g_csr[j];
        float w0 = __int_as_float(e0.y);
        uint2 v0 = in2[(size_t)e0.x * 32 + lane];
        float2 u0 = __half22float2(*reinterpret_cast<__half2*>(&v0.x));
        float2 u1 = __half22float2(*reinterpret_cast<__half2*>(&v0.y));
        a0 += u0.x * w0; a1 += u0.y * w0; a2 += u1.x * w0; a3 += u1.y * w0;
    }
    float4 b = *(const float4*)(bias + lane * 4);
    a0 = fmaxf(a0 + b.x, 0.f); a1 = fmaxf(a1 + b.y, 0.f);
    a2 = fmaxf(a2 + b.z, 0.f); a3 = fmaxf(a3 + b.w, 0.f);
    if (LAST) {
        float4 w3 = *(const float4*)(W3 + lane * 4);
        float s = a0 * w3.x + a1 * w3.y + a2 * w3.z + a3 * w3.w;
#pragma unroll
        for (int off = 16; off > 0; off >>= 1) s += __shfl_xor_sync(0xffffffffu, s, off);
        if (lane == 0) tout[node] = s;
    } else {
        __half2 o0 = __floats2half2_rn(a0, a1);
        __half2 o1 = __floats2half2_rn(a2, a3);
        uint2 ov;
        ov.x = *reinterpret_cast<uint32_t*>(&o0);
        ov.y = *reinterpret_cast<uint32_t*>(&o1);
        ((uint2*)out)[(size_t)node * 32 + lane] = ov;
    }
}

// ---------------- fp16 tensor-core GEMM ----------------
#define MMA_F16(d, a0, a1, a2, a3, b0, b1)                                  \
    asm volatile("mma.sync.aligned.m16n8k16.row.col.f32.f16.f16.f32 "       \
                 "{%0,%1,%2,%3}, {%4,%5,%6,%7}, {%8,%9}, {%0,%1,%2,%3};"    \
                 : "+f"(d[0]), "+f"(d[1]), "+f"(d[2]), "+f"(d[3])           \
                 : "r"(a0), "r"(a1), "r"(a2), "r"(a3), "r"(b0), "r"(b1))

template <int K, bool BIASRELU>
__global__ void __launch_bounds__(256, 2)
k_gemm16(const __half* __restrict__ A, const __half* __restrict__ BhiT,
         const __half* __restrict__ BloT, const float* __restrict__ bias,
         __half* __restrict__ Cout) {
    __shared__ __half As[128 * AST];
    __shared__ __half Bhi[128 * BST];
    __shared__ __half Blo[128 * BST];

    int tid = threadIdx.x;
    int wid = tid >> 5, lane = tid & 31;
    int wr = wid >> 1, wc = wid & 1;
    int row0 = blockIdx.x * 128;
    int mrow = wr * 32;
    int ncol = wc * 64;
    int lq = lane >> 2;
    int lr = lane & 3;

    float acc[2][8][4];
#pragma unroll
    for (int ma = 0; ma < 2; ma++)
#pragma unroll
        for (int na = 0; na < 8; na++)
#pragma unroll
            for (int r = 0; r < 4; r++) acc[ma][na][r] = 0.0f;

    for (int k0 = 0; k0 < K; k0 += 32) {
#pragma unroll
        for (int i = 0; i < 2; i++) {
            int li = tid + i * 256;
            int r = li >> 2;
            int c = (li & 3) * 8;
            uint4 v = make_uint4(0, 0, 0, 0);
            int gr = row0 + r;
            if (gr < NN) v = *(const uint4*)(A + (size_t)gr * K + k0 + c);
            *(uint4*)&As[r * AST + c] = v;
        }
#pragma unroll
        for (int i = 0; i < 2; i++) {
            int li = tid + i * 256;
            int n = li >> 2;
            int c = (li & 3) * 8;
            *(uint4*)&Bhi[n * BST + c] = *(const uint4*)(BhiT + (size_t)n * K + k0 + c);
            *(uint4*)&Blo[n * BST + c] = *(const uint4*)(BloT + (size_t)n * K + k0 + c);
        }
        __syncthreads();
#pragma unroll
        for (int ks = 0; ks < 2; ks++) {
            int kk = ks * 16;
            uint32_t a[2][4];
#pragma unroll
            for (int ma = 0; ma < 2; ma++) {
                int rb = mrow + ma * 16;
                a[ma][0] = *(const uint32_t*)&As[(rb + lq) * AST + kk + 2 * lr];
                a[ma][1] = *(const uint32_t*)&As[(rb + lq + 8) * AST + kk + 2 * lr];
                a[ma][2] = *(const uint32_t*)&As[(rb + lq) * AST + kk + 2 * lr + 8];
                a[ma][3] = *(const uint32_t*)&As[(rb + lq + 8) * AST + kk + 2 * lr + 8];
            }
#pragma unroll
            for (int na = 0; na < 8; na++) {
                int n = ncol + na * 8 + lq;
                uint32_t bh0 = *(const uint32_t*)&Bhi[n * BST + kk + 2 * lr];
                uint32_t bh1 = *(const uint32_t*)&Bhi[n * BST + kk + 2 * lr + 8];
                uint32_t bl0 = *(const uint32_t*)&Blo[n * BST + kk + 2 * lr];
                uint32_t bl1 = *(const uint32_t*)&Blo[n * BST + kk + 2 * lr + 8];
#pragma unroll
                for (int ma = 0; ma < 2; ma++) {
                    MMA_F16(acc[ma][na], a[ma][0], a[ma][1], a[ma][2], a[ma][3], bh0, bh1);
                    MMA_F16(acc[ma][na], a[ma][0], a[ma][1], a[ma][2], a[ma][3], bl0, bl1);
                }
            }
        }
        __syncthreads();
    }
#pragma unroll
    for (int ma = 0; ma < 2; ma++) {
        int r0 = row0 + mrow + ma * 16 + lq;
#pragma unroll
        for (int na = 0; na < 8; na++) {
            int col = ncol + na * 8 + 2 * lr;
            float c0 = acc[ma][na][0], c1 = acc[ma][na][1];
            float c2 = acc[ma][na][2], c3 = acc[ma][na][3];
            if (BIASRELU) {
                float bx = bias[col], by = bias[col + 1];
                c0 = fmaxf(c0 + bx, 0.f); c1 = fmaxf(c1 + by, 0.f);
                c2 = fmaxf(c2 + bx, 0.f); c3 = fmaxf(c3 + by, 0.f);
            }
            if (r0 < NN)     *(__half2*)(Cout + (size_t)r0 * 128 + col) = __floats2half2_rn(c0, c1);
            if (r0 + 8 < NN) *(__half2*)(Cout + (size_t)(r0 + 8) * 128 + col) = __floats2half2_rn(c2, c3);
        }
    }
}

// ---------------- output: F=1 gather ----------------
__global__ void k_final(const float* __restrict__ t, const float* __restrict__ b3,
                        float* __restrict__ out) {
    int i = blockIdx.x * blockDim.x + threadIdx.x;
    if (i >= NN) return;
    float di = g_dinv[i];
    float s = t[i] * di * di + b3[0];
    int j = g_rowptr[i], end = g_rowptr[i + 1];
    for (; j < end; j++) {
        int2 e = g_csr[j];
        s += t[e.x] * __int_as_float(e.y);
    }
    out[i] = s;
}

// ---------------- launch ----------------
extern "C" void kernel_launch(void* const* d_in, const int* in_sizes, int n_in,
                              void* d_out, int out_size) {
    const float* x  = (const float*)d_in[0];
    const int* ei   = (const int*)d_in[1];
    const float* W1 = (const float*)d_in[2];
    const float* b1 = (const float*)d_in[3];
    const float* W2 = (const float*)d_in[4];
    const float* b2 = (const float*)d_in[5];
    const float* W3 = (const float*)d_in[6];
    const float* b3 = (const float*)d_in[7];
    float* out = (float*)d_out;

    const int* src = ei;
    const int* dst = ei + EE;

    __half* x16;  cudaGetSymbolAddress((void**)&x16, g_x16);
    __half* a64;  cudaGetSymbolAddress((void**)&a64, g_a64);
    __half* h16;  cudaGetSymbolAddress((void**)&h16, g_h16);
    __half* g16;  cudaGetSymbolAddress((void**)&g16, g_g16);
    __half* whiT; cudaGetSymbolAddress((void**)&whiT, g_WhiT);
    __half* wloT; cudaGetSymbolAddress((void**)&wloT, g_WloT);
    float* tbuf;  cudaGetSymbolAddress((void**)&tbuf, g_t);
    int* cntp;    cudaGetSymbolAddress((void**)&cntp, g_cnt);

    // side stream + fork/join events (lazy init, never destroyed; identity of
    // streams doesn't change the captured work)
    static cudaStream_t s2 = nullptr;
    static cudaEvent_t evFork = nullptr, evJoin = nullptr;
    if (!s2) {
        cudaStreamCreateWithFlags(&s2, cudaStreamNonBlocking);
        cudaEventCreateWithFlags(&evFork, cudaEventDisableTiming);
        cudaEventCreateWithFlags(&evJoin, cudaEventDisableTiming);
    }

    // fork: CSR chain on s2, prep on main stream — independent
    cudaEventRecord(evFork, 0);
    cudaStreamWaitEvent(s2, evFork, 0);

    cudaMemsetAsync(cntp, 0, (NN + 1) * sizeof(int), s2);
    k_hist<<<(EE / 4 + 255) / 256, 256, 0, s2>>>(dst);
    k_scan1<<<NSCAN, SCAN_BLK, 0, s2>>>();
    k_scan3<<<(NN + 255) / 256, 256, 0, s2>>>();
    k_scatter<<<(EE / 4 + 255) / 256, 256, 0, s2>>>(src, dst);
    cudaEventRecord(evJoin, s2);

    k_prep<<<(XQUAD + 255) / 256, 256>>>(x, W1, W2);

    // join before anything that needs the CSR
    cudaStreamWaitEvent(0, evJoin, 0);

    const int GB = (NN + 127) / 128;

    // layer 1: agg-first at F=64 fp16, then GEMM 64->128 with b1+relu
    k_agg64<<<(NN + 7) / 8, 256>>>(x16, a64);
    k_gemm16<FIN, true><<<GB, 256>>>(a64, whiT, wloT, b1, h16);

    // hidden layers: GEMM (no bias) then agg128 (bias+relu); last agg fuses matvec
    for (int l = 0; l < NLAYER; l++) {
        const __half* bh = whiT + FIN * HD + (size_t)l * HD * HD;
        const __half* bl = wloT + FIN * HD + (size_t)l * HD * HD;
        k_gemm16<HD, false><<<GB, 256>>>(h16, bh, bl, nullptr, g16);
        if (l < NLAYER - 1)
            k_agg128<false><<<(NN + 7) / 8, 256>>>(g16, b2 + (size_t)l * HD,
                                                   h16, nullptr, nullptr);
        else
            k_agg128<true><<<(NN + 7) / 8, 256>>>(g16, b2 + (size_t)l * HD,
                                                  nullptr, W3, tbuf);
    }

    // output: F=1 gather + b3
    k_final<<<(NN + 255) / 256, 256>>>(tbuf, b3, out);
}